// round 12
// baseline (speedup 1.0000x reference)
#include <cuda_runtime.h>
#include <cuda_bf16.h>

#define N_NODES 100000
#define N_EDGES 800000
#define N_GRAPHS 2048
#define EMB 300
#define EMB4 75      // EMB / 4
#define FEAT 256
#define N_LAYERS 5
#define BN_EPS 1e-5f

// ---------------- static scratch ----------------
__device__ __align__(16) float g_h[(size_t)N_NODES * EMB];    // 120 MB
__device__ __align__(16) float g_agg[(size_t)N_NODES * EMB];  // 120 MB
__device__ int   g_deg[N_NODES];
__device__ int   g_off[N_NODES + 1];
__device__ int   g_cur[N_NODES];
__device__ float g_dinv[N_NODES];
__device__ int   g_src[N_EDGES];
__device__ float g_nrm[N_EDGES];
__device__ int   g_bsum[128];
__device__ __align__(16) float g_colsum[EMB];
__device__ __align__(16) float g_colsq[EMB];
__device__ __align__(16) float g_scale[EMB];
__device__ __align__(16) float g_shift[EMB];
__device__ float g_pool[(size_t)N_GRAPHS * EMB];
__device__ float g_cnt[N_GRAPHS];

// ---------------- graph preprocessing ----------------
__global__ void k_zero_deg() {
    int i = blockIdx.x * blockDim.x + threadIdx.x;
    if (i < N_NODES) g_deg[i] = 0;
}

__global__ void k_hist(const int* __restrict__ ei) {
    int e = blockIdx.x * blockDim.x + threadIdx.x;
    if (e < N_EDGES) atomicAdd(&g_deg[ei[N_EDGES + e]], 1);
}

__global__ void k_dinv() {
    int i = blockIdx.x * blockDim.x + threadIdx.x;
    if (i < N_NODES) g_dinv[i] = rsqrtf((float)g_deg[i] + 1.0f);
}

// ---- parallel 3-phase scan ----
#define SCAN_CHUNK 1024
#define N_CHUNKS ((N_NODES + SCAN_CHUNK - 1) / SCAN_CHUNK)  // 98

__global__ void k_chunksum() {
    __shared__ int s[1024];
    int b = blockIdx.x, t = threadIdx.x;
    int idx = b * SCAN_CHUNK + t;
    s[t] = (idx < N_NODES) ? g_deg[idx] : 0;
    __syncthreads();
    for (int d = 512; d > 0; d >>= 1) {
        if (t < d) s[t] += s[t + d];
        __syncthreads();
    }
    if (t == 0) g_bsum[b] = s[0];
}

__global__ void k_scanb() {
    __shared__ int s[128];
    int t = threadIdx.x;
    s[t] = (t < N_CHUNKS) ? g_bsum[t] : 0;
    __syncthreads();
    for (int d = 1; d < 128; d <<= 1) {
        int v = (t >= d) ? s[t - d] : 0;
        __syncthreads();
        s[t] += v;
        __syncthreads();
    }
    int v = (t < N_CHUNKS) ? ((t > 0) ? s[t - 1] : 0) : 0;
    if (t < N_CHUNKS) g_bsum[t] = v;
    if (t == 0) g_off[N_NODES] = N_EDGES;
}

__global__ void k_chunkscan() {
    __shared__ int s[1024];
    int b = blockIdx.x, t = threadIdx.x;
    int idx = b * SCAN_CHUNK + t;
    int v = (idx < N_NODES) ? g_deg[idx] : 0;
    s[t] = v;
    __syncthreads();
    for (int d = 1; d < 1024; d <<= 1) {
        int u = (t >= d) ? s[t - d] : 0;
        __syncthreads();
        s[t] += u;
        __syncthreads();
    }
    if (idx < N_NODES) {
        int o = g_bsum[b] + s[t] - v;  // exclusive
        g_off[idx] = o;
        g_cur[idx] = o;
    }
}

__global__ void k_fill(const int* __restrict__ ei) {
    int e = blockIdx.x * blockDim.x + threadIdx.x;
    if (e >= N_EDGES) return;
    int r = ei[e];
    int c = ei[N_EDGES + e];
    int pos = atomicAdd(&g_cur[c], 1);
    g_src[pos] = r;
    g_nrm[pos] = g_dinv[r] * g_dinv[c];
}

// ---------------- h init ----------------
__global__ void k_init_h(const int* __restrict__ x,
                         const float* __restrict__ emb1,
                         const float* __restrict__ emb2) {
    int v = blockIdx.x;
    int t = threadIdx.x;
    if (t >= EMB4) return;
    int x0 = x[v * 2];
    int x1 = x[v * 2 + 1];
    float4 a = ((const float4*)(emb1 + (size_t)x0 * EMB))[t];
    float4 b = ((const float4*)(emb2 + (size_t)x1 * EMB))[t];
    float4 o;
    o.x = a.x + b.x; o.y = a.y + b.y; o.z = a.z + b.z; o.w = a.w + b.w;
    ((float4*)(g_h + (size_t)v * EMB))[t] = o;
}

// ---------------- aggregation: warp-per-node, fused BN+ReLU ----------------
__global__ void k_agg(int mode) {
    int warp = (blockIdx.x * blockDim.x + threadIdx.x) >> 5;
    int lane = threadIdx.x & 31;
    if (warp >= N_NODES) return;
    bool third = (lane < EMB4 - 64);

    float4 sc0 = {1,1,1,1}, sc1 = {1,1,1,1}, sc2 = {1,1,1,1};
    float4 sh0 = {0,0,0,0}, sh1 = {0,0,0,0}, sh2 = {0,0,0,0};
    if (mode) {
        sc0 = ((const float4*)g_scale)[lane];
        sc1 = ((const float4*)g_scale)[lane + 32];
        sh0 = ((const float4*)g_shift)[lane];
        sh1 = ((const float4*)g_shift)[lane + 32];
        if (third) {
            sc2 = ((const float4*)g_scale)[lane + 64];
            sh2 = ((const float4*)g_shift)[lane + 64];
        }
    }

#define APPLY(v, sc, sh)                                           \
    if (mode) {                                                    \
        v.x = fmaxf(fmaf(v.x, sc.x, sh.x), 0.0f);                  \
        v.y = fmaxf(fmaf(v.y, sc.y, sh.y), 0.0f);                  \
        v.z = fmaxf(fmaf(v.z, sc.z, sh.z), 0.0f);                  \
        v.w = fmaxf(fmaf(v.w, sc.w, sh.w), 0.0f);                  \
    }

    float di = g_dinv[warp];
    float dsq = di * di;
    float4 acc0 = {0,0,0,0}, acc1 = {0,0,0,0}, acc2 = {0,0,0,0};
    {
        const float4* hv = (const float4*)(g_h + (size_t)warp * EMB);
        float4 t0 = hv[lane];
        float4 t1 = hv[lane + 32];
        APPLY(t0, sc0, sh0); APPLY(t1, sc1, sh1);
        acc0.x = dsq * t0.x; acc0.y = dsq * t0.y; acc0.z = dsq * t0.z; acc0.w = dsq * t0.w;
        acc1.x = dsq * t1.x; acc1.y = dsq * t1.y; acc1.z = dsq * t1.z; acc1.w = dsq * t1.w;
        if (third) {
            float4 t2 = hv[lane + 64];
            APPLY(t2, sc2, sh2);
            acc2.x = dsq * t2.x; acc2.y = dsq * t2.y; acc2.z = dsq * t2.z; acc2.w = dsq * t2.w;
        }
    }
    int e0 = g_off[warp], e1 = g_off[warp + 1];
#pragma unroll 2
    for (int e = e0; e < e1; e++) {
        int s = g_src[e];
        float w = g_nrm[e];
        const float4* hs = (const float4*)(g_h + (size_t)s * EMB);
        float4 t0 = hs[lane];
        float4 t1 = hs[lane + 32];
        APPLY(t0, sc0, sh0); APPLY(t1, sc1, sh1);
        acc0.x += w * t0.x; acc0.y += w * t0.y; acc0.z += w * t0.z; acc0.w += w * t0.w;
        acc1.x += w * t1.x; acc1.y += w * t1.y; acc1.z += w * t1.z; acc1.w += w * t1.w;
        if (third) {
            float4 t2 = hs[lane + 64];
            APPLY(t2, sc2, sh2);
            acc2.x += w * t2.x; acc2.y += w * t2.y; acc2.z += w * t2.z; acc2.w += w * t2.w;
        }
    }
#undef APPLY
    float4* ap = (float4*)(g_agg + (size_t)warp * EMB);
    ap[lane] = acc0;
    ap[lane + 32] = acc1;
    if (third) ap[lane + 64] = acc2;
}

// ---------------- stats ----------------
__global__ void k_zero_stats() {
    int i = threadIdx.x;
    if (i < EMB) { g_colsum[i] = 0.0f; g_colsq[i] = 0.0f; }
}

__global__ void k_finstats(const float* __restrict__ gamma,
                           const float* __restrict__ beta) {
    int c = threadIdx.x;
    if (c >= EMB) return;
    const float invN = 1.0f / (float)N_NODES;
    float mean = g_colsum[c] * invN;
    float var = g_colsq[c] * invN - mean * mean;
    float sc = gamma[c] * rsqrtf(var + BN_EPS);
    g_scale[c] = sc;
    g_shift[c] = beta[c] - mean * sc;
}

// ---- split-BF16 GEMM, pre-split bf16 staged in SMEM (zero in-loop cvt) ----
#define GM 128
#define GN 64
#define GK 32
#define APITCH 40   // bf16 elems per A row; m*20+cc spans all 32 banks
#define BPITCH 40   // bf16 elems per B row (B stored [n][k])
#define AP2 (APITCH / 2)
#define BP2 (BPITCH / 2)
// bf16 elem counts (2 buffers each)
#define AS_ELEMS (2 * GM * APITCH)   // 10240
#define BS_ELEMS (2 * GN * BPITCH)   // 5120
#define GEMM_SMEM_BYTES ((AS_ELEMS * 2 + BS_ELEMS * 2) * 2)  // hi+lo, 2B each = 61440

// split 2 floats into packed bf16x2 hi and lo (low half = first element)
__device__ __forceinline__ void split_bf2(float x, float y, unsigned& hi, unsigned& lo) {
    __nv_bfloat162 h = __floats2bfloat162_rn(x, y);
    float hx = __low2float(h), hy = __high2float(h);
    __nv_bfloat162 l = __floats2bfloat162_rn(x - hx, y - hy);
    hi = *(unsigned*)&h;
    lo = *(unsigned*)&l;
}

__device__ __forceinline__ void split_bf1(float x, __nv_bfloat16& hi, __nv_bfloat16& lo) {
    hi = __float2bfloat16_rn(x);
    lo = __float2bfloat16_rn(x - __bfloat162float(hi));
}

#define MMAB(d, A0, A1, A2, A3, B0, B1)                                        \
    asm volatile(                                                              \
        "mma.sync.aligned.m16n8k16.row.col.f32.bf16.bf16.f32 "                 \
        "{%0,%1,%2,%3}, {%4,%5,%6,%7}, {%8,%9}, {%0,%1,%2,%3};\n"              \
        : "+f"(d[0]), "+f"(d[1]), "+f"(d[2]), "+f"(d[3])                       \
        : "r"(A0), "r"(A1), "r"(A2), "r"(A3), "r"(B0), "r"(B1))

__global__ __launch_bounds__(256, 2)
void k_gemm_bf16(const float* __restrict__ W, const float* __restrict__ bias) {
    extern __shared__ __align__(16) __nv_bfloat16 smb[];
    __nv_bfloat16* AsH = smb;                      // [2][GM][APITCH]
    __nv_bfloat16* AsL = AsH + AS_ELEMS;
    __nv_bfloat16* BsH = AsL + AS_ELEMS;           // [2][GN][BPITCH]  ([n][k])
    __nv_bfloat16* BsL = BsH + BS_ELEMS;
    unsigned* AsHu = (unsigned*)AsH;
    unsigned* AsLu = (unsigned*)AsL;
    const unsigned* BsHu = (const unsigned*)BsH;
    const unsigned* BsLu = (const unsigned*)BsL;

    const float* A = g_agg;
    float* C = g_h;

    int tid = threadIdx.x;
    int warp = tid >> 5, lane = tid & 31;
    int r0 = lane >> 2, cc = lane & 3;
    int mBase = blockIdx.y * GM;
    int nBase = blockIdx.x * GN;
    int warpM = (warp & 3) * 32;
    int warpN = (warp >> 2) * 32;

    float acc[2][4][4];
#pragma unroll
    for (int mi = 0; mi < 2; mi++)
#pragma unroll
        for (int ni = 0; ni < 4; ni++)
#pragma unroll
            for (int i = 0; i < 4; i++) acc[mi][ni][i] = 0.0f;

    int aRow = tid >> 1;
    int aCol = (tid & 1) * 16;
    const int NKT = 10;  // 10 * 32 = 320 >= 300

    float4 pa[4], pb[2];

#define LOAD_TILE(kt)                                                          \
    {                                                                          \
        int k0 = (kt) * GK;                                                    \
        int grow = mBase + aRow;                                               \
        bool rok = grow < N_NODES;                                             \
        _Pragma("unroll")                                                      \
        for (int i = 0; i < 4; i++) {                                          \
            int gk = k0 + aCol + i * 4;                                        \
            if (rok && gk < EMB)                                               \
                pa[i] = *(const float4*)(A + (size_t)grow * EMB + gk);         \
            else                                                               \
                pa[i] = make_float4(0, 0, 0, 0);                               \
        }                                                                      \
        _Pragma("unroll")                                                      \
        for (int i = 0; i < 2; i++) {                                          \
            int f4 = tid * 2 + i;                                              \
            int br = f4 >> 4;                                                  \
            int bc = (f4 & 15) * 4;                                            \
            int gk = k0 + br;                                                  \
            int gn = nBase + bc;                                               \
            if (gk < EMB && gn < EMB)                                          \
                pb[i] = *(const float4*)(W + (size_t)gk * EMB + gn);           \
            else                                                               \
                pb[i] = make_float4(0, 0, 0, 0);                               \
        }                                                                      \
    }

// convert + store pre-split bf16; A as [m][k], B transposed to [n][k]
#define STORE_TILE(buf)                                                        \
    {                                                                          \
        int abase = (buf) * (GM * AP2) + aRow * AP2 + (aCol >> 1);             \
        _Pragma("unroll")                                                      \
        for (int i = 0; i < 4; i++) {                                          \
            unsigned h0, l0, h1, l1;                                           \
            split_bf2(pa[i].x, pa[i].y, h0, l0);                               \
            split_bf2(pa[i].z, pa[i].w, h1, l1);                               \
            AsHu[abase + i * 2]     = h0;                                      \
            AsHu[abase + i * 2 + 1] = h1;                                      \
            AsLu[abase + i * 2]     = l0;                                      \
            AsLu[abase + i * 2 + 1] = l1;                                      \
        }                                                                      \
        _Pragma("unroll")                                                      \
        for (int i = 0; i < 2; i++) {                                          \
            int f4 = tid * 2 + i;                                              \
            int br = f4 >> 4;                                                  \
            int bc = (f4 & 15) * 4;                                            \
            float vv[4] = {pb[i].x, pb[i].y, pb[i].z, pb[i].w};                \
            _Pragma("unroll")                                                  \
            for (int j = 0; j < 4; j++) {                                      \
                __nv_bfloat16 h, l;                                            \
                split_bf1(vv[j], h, l);                                        \
                int bo = (buf) * (GN * BPITCH) + (bc + j) * BPITCH + br;       \
                BsH[bo] = h;                                                   \
                BsL[bo] = l;                                                   \
            }                                                                  \
        }                                                                      \
    }

    LOAD_TILE(0);
    STORE_TILE(0);
    __syncthreads();

    for (int kt = 0; kt < NKT; kt++) {
        int buf = kt & 1;
        if (kt + 1 < NKT) LOAD_TILE(kt + 1);
        int aub = buf * (GM * AP2);
        int bub = buf * (GN * BP2);
#pragma unroll
        for (int ks = 0; ks < 2; ks++) {
            int kh = ks * 8 + cc;  // uint (k-pair) index
            unsigned ah[2][4], al[2][4], bh[4][2], bl[4][2];
#pragma unroll
            for (int mi = 0; mi < 2; mi++) {
                int mr = warpM + mi * 16 + r0;
                int i0 = aub + mr * AP2 + kh;
                int i1 = aub + (mr + 8) * AP2 + kh;
                ah[mi][0] = AsHu[i0];     al[mi][0] = AsLu[i0];
                ah[mi][1] = AsHu[i1];     al[mi][1] = AsLu[i1];
                ah[mi][2] = AsHu[i0 + 4]; al[mi][2] = AsLu[i0 + 4];
                ah[mi][3] = AsHu[i1 + 4]; al[mi][3] = AsLu[i1 + 4];
            }
#pragma unroll
            for (int ni = 0; ni < 4; ni++) {
                int nc = warpN + ni * 8 + r0;
                int i0 = bub + nc * BP2 + kh;
                bh[ni][0] = BsHu[i0];     bl[ni][0] = BsLu[i0];
                bh[ni][1] = BsHu[i0 + 4]; bl[ni][1] = BsLu[i0 + 4];
            }
#pragma unroll
            for (int mi = 0; mi < 2; mi++)
#pragma unroll
                for (int ni = 0; ni < 4; ni++) {
                    // small terms first, hi*hi last
                    MMAB(acc[mi][ni], al[mi][0], al[mi][1], al[mi][2], al[mi][3],
                         bh[ni][0], bh[ni][1]);
                    MMAB(acc[mi][ni], ah[mi][0], ah[mi][1], ah[mi][2], ah[mi][3],
                         bl[ni][0], bl[ni][1]);
                    MMAB(acc[mi][ni], ah[mi][0], ah[mi][1], ah[mi][2], ah[mi][3],
                         bh[ni][0], bh[ni][1]);
                }
        }
        if (kt + 1 < NKT) STORE_TILE(1 - buf);
        __syncthreads();
    }

    // epilogue: bias, store, column stats (shfl-reduced before global atomics)
#pragma unroll
    for (int ni = 0; ni < 4; ni++) {
        int gcol = nBase + warpN + ni * 8 + 2 * cc;
        bool cok = gcol < EMB;  // gcol even, EMB even -> gcol+1 valid too
        float b0 = cok ? bias[gcol] : 0.0f;
        float b1 = cok ? bias[gcol + 1] : 0.0f;
        float s0 = 0.0f, s1 = 0.0f, q0 = 0.0f, q1 = 0.0f;
#pragma unroll
        for (int mi = 0; mi < 2; mi++) {
            int grow0 = mBase + warpM + mi * 16 + r0;
            int grow1 = grow0 + 8;
            float v00 = acc[mi][ni][0] + b0;
            float v01 = acc[mi][ni][1] + b1;
            float v10 = acc[mi][ni][2] + b0;
            float v11 = acc[mi][ni][3] + b1;
            if (cok && grow0 < N_NODES) {
                *(float2*)(C + (size_t)grow0 * EMB + gcol) = make_float2(v00, v01);
                s0 += v00; s1 += v01; q0 += v00 * v00; q1 += v01 * v01;
            }
            if (cok && grow1 < N_NODES) {
                *(float2*)(C + (size_t)grow1 * EMB + gcol) = make_float2(v10, v11);
                s0 += v10; s1 += v11; q0 += v10 * v10; q1 += v11 * v11;
            }
        }
#pragma unroll
        for (int d = 4; d < 32; d <<= 1) {
            s0 += __shfl_xor_sync(0xffffffffu, s0, d);
            s1 += __shfl_xor_sync(0xffffffffu, s1, d);
            q0 += __shfl_xor_sync(0xffffffffu, q0, d);
            q1 += __shfl_xor_sync(0xffffffffu, q1, d);
        }
        if (r0 == 0 && cok) {
            atomicAdd(&g_colsum[gcol], s0);
            atomicAdd(&g_colsum[gcol + 1], s1);
            atomicAdd(&g_colsq[gcol], q0);
            atomicAdd(&g_colsq[gcol + 1], q1);
        }
    }
#undef LOAD_TILE
#undef STORE_TILE
}

// ---------------- pooling (fused final BN, no relu) ----------------
__global__ void k_zero_pool() {
    int i = blockIdx.x * blockDim.x + threadIdx.x;
    if (i < N_GRAPHS * EMB) g_pool[i] = 0.0f;
    if (i < N_GRAPHS) g_cnt[i] = 0.0f;
}

__global__ void k_count(const int* __restrict__ batch) {
    int i = blockIdx.x * blockDim.x + threadIdx.x;
    if (i < N_NODES) atomicAdd(&g_cnt[batch[i]], 1.0f);
}

#define PCHUNK 256
__global__ void k_poolsum(const int* __restrict__ batch) {
    __shared__ int sb[PCHUNK];
    int t = threadIdx.x;
    int base = blockIdx.x * PCHUNK;
    int end = base + PCHUNK;
    if (end > N_NODES) end = N_NODES;
    int len = end - base;
    for (int i = t; i < len; i += blockDim.x) sb[i] = batch[base + i];
    __syncthreads();
    if (t >= EMB) return;
    float sc = g_scale[t], sh = g_shift[t];
    float acc = 0.0f;
    int cur = sb[0];
    for (int n = 0; n < len; n++) {
        int gph = sb[n];
        if (gph != cur) {
            atomicAdd(&g_pool[(size_t)cur * EMB + t], acc);
            acc = 0.0f;
            cur = gph;
        }
        acc += fmaf(g_h[(size_t)(base + n) * EMB + t], sc, sh);
    }
    atomicAdd(&g_pool[(size_t)cur * EMB + t], acc);
}

// ---------------- final projection ----------------
__global__ void k_final(const float* __restrict__ Wf,
                        const float* __restrict__ bf,
                        float* __restrict__ out) {
    __shared__ float p[EMB];
    int gph = blockIdx.x;
    int f = threadIdx.x;
    float inv = 1.0f / fmaxf(g_cnt[gph], 1.0f);
    for (int j = f; j < EMB; j += FEAT) p[j] = g_pool[(size_t)gph * EMB + j] * inv;
    __syncthreads();
    float acc = bf[f];
#pragma unroll 4
    for (int j = 0; j < EMB; j++) acc += p[j] * Wf[(size_t)j * FEAT + f];
    out[(size_t)gph * FEAT + f] = acc;
}

// ---------------- launcher ----------------
extern "C" void kernel_launch(void* const* d_in, const int* in_sizes, int n_in,
                              void* d_out, int out_size) {
    const int*   x      = (const int*)d_in[0];
    const int*   ei     = (const int*)d_in[1];
    const int*   batch  = (const int*)d_in[2];
    const float* emb1   = (const float*)d_in[3];
    const float* emb2   = (const float*)d_in[4];
    const float* Ws     = (const float*)d_in[5];
    const float* bs     = (const float*)d_in[6];
    const float* gammas = (const float*)d_in[7];
    const float* betas  = (const float*)d_in[8];
    const float* Wf     = (const float*)d_in[9];
    const float* bf     = (const float*)d_in[10];
    float* out = (float*)d_out;

    cudaFuncSetAttribute(k_gemm_bf16,
                         cudaFuncAttributeMaxDynamicSharedMemorySize,
                         GEMM_SMEM_BYTES);

    // graph preprocessing (CSR by destination)
    k_zero_deg<<<(N_NODES + 255) / 256, 256>>>();
    k_hist<<<(N_EDGES + 255) / 256, 256>>>(ei);
    k_dinv<<<(N_NODES + 255) / 256, 256>>>();
    k_chunksum<<<N_CHUNKS, 1024>>>();
    k_scanb<<<1, 128>>>();
    k_chunkscan<<<N_CHUNKS, 1024>>>();
    k_fill<<<(N_EDGES + 255) / 256, 256>>>(ei);

    // h init
    k_init_h<<<N_NODES, 96>>>(x, emb1, emb2);

    dim3 gemmGrid((EMB + GN - 1) / GN, (N_NODES + GM - 1) / GM);  // n fastest: A tile L2-reuse
    for (int l = 0; l < N_LAYERS; l++) {
        const float* W = Ws + (size_t)l * EMB * EMB;
        const float* b = bs + (size_t)l * EMB;
        const float* gamma = gammas + (size_t)l * EMB;
        const float* beta = betas + (size_t)l * EMB;
        k_agg<<<(N_NODES * 32 + 255) / 256, 256>>>(l == 0 ? 0 : 1);
        k_zero_stats<<<1, 320>>>();
        k_gemm_bf16<<<gemmGrid, 256, GEMM_SMEM_BYTES>>>(W, b);
        k_finstats<<<1, 320>>>(gamma, beta);
    }

    // pooling (applies final BN) + projection
    k_zero_pool<<<(N_GRAPHS * EMB + 255) / 256, 256>>>();
    k_count<<<(N_NODES + 255) / 256, 256>>>(batch);
    k_poolsum<<<(N_NODES + PCHUNK - 1) / PCHUNK, 320>>>(batch);
    k_final<<<N_GRAPHS, FEAT>>>(Wf, bf, out);
}

// round 13
// speedup vs baseline: 1.2650x; 1.2650x over previous
#include <cuda_runtime.h>
#include <cuda_bf16.h>

#define N_NODES 100000
#define N_EDGES 800000
#define N_GRAPHS 2048
#define EMB 300
#define EMB4 75      // EMB / 4
#define EMBP 150     // bf16x2 (hi,lo) pairs per row = EMB/2
#define FEAT 256
#define N_LAYERS 5
#define BN_EPS 1e-5f

// split 2 floats into packed bf16x2 hi and lo (low half = first element)
__device__ __forceinline__ void split_bf2(float x, float y, unsigned& hi, unsigned& lo) {
    __nv_bfloat162 h = __floats2bfloat162_rn(x, y);
    float hx = __low2float(h), hy = __high2float(h);
    __nv_bfloat162 l = __floats2bfloat162_rn(x - hx, y - hy);
    hi = *(unsigned*)&h;
    lo = *(unsigned*)&l;
}

// ---------------- static scratch ----------------
__device__ __align__(16) float g_h[(size_t)N_NODES * EMB];     // 120 MB
__device__ __align__(16) uint2 g_aggP[(size_t)N_NODES * EMBP]; // 120 MB: (hi,lo) bf16x2 pairs
__device__ int   g_deg[N_NODES];
__device__ int   g_off[N_NODES + 1];
__device__ int   g_cur[N_NODES];
__device__ float g_dinv[N_NODES];
__device__ int   g_src[N_EDGES];
__device__ float g_nrm[N_EDGES];
__device__ int   g_bsum[128];
__device__ __align__(16) float g_colsum[EMB];
__device__ __align__(16) float g_colsq[EMB];
__device__ __align__(16) float g_scale[EMB];
__device__ __align__(16) float g_shift[EMB];
__device__ float g_pool[(size_t)N_GRAPHS * EMB];
__device__ float g_cnt[N_GRAPHS];

// ---------------- graph preprocessing ----------------
__global__ void k_zero_deg() {
    int i = blockIdx.x * blockDim.x + threadIdx.x;
    if (i < N_NODES) g_deg[i] = 0;
}

__global__ void k_hist(const int* __restrict__ ei) {
    int e = blockIdx.x * blockDim.x + threadIdx.x;
    if (e < N_EDGES) atomicAdd(&g_deg[ei[N_EDGES + e]], 1);
}

__global__ void k_dinv() {
    int i = blockIdx.x * blockDim.x + threadIdx.x;
    if (i < N_NODES) g_dinv[i] = rsqrtf((float)g_deg[i] + 1.0f);
}

// ---- parallel 3-phase scan ----
#define SCAN_CHUNK 1024
#define N_CHUNKS ((N_NODES + SCAN_CHUNK - 1) / SCAN_CHUNK)  // 98

__global__ void k_chunksum() {
    __shared__ int s[1024];
    int b = blockIdx.x, t = threadIdx.x;
    int idx = b * SCAN_CHUNK + t;
    s[t] = (idx < N_NODES) ? g_deg[idx] : 0;
    __syncthreads();
    for (int d = 512; d > 0; d >>= 1) {
        if (t < d) s[t] += s[t + d];
        __syncthreads();
    }
    if (t == 0) g_bsum[b] = s[0];
}

__global__ void k_scanb() {
    __shared__ int s[128];
    int t = threadIdx.x;
    s[t] = (t < N_CHUNKS) ? g_bsum[t] : 0;
    __syncthreads();
    for (int d = 1; d < 128; d <<= 1) {
        int v = (t >= d) ? s[t - d] : 0;
        __syncthreads();
        s[t] += v;
        __syncthreads();
    }
    int v = (t < N_CHUNKS) ? ((t > 0) ? s[t - 1] : 0) : 0;
    if (t < N_CHUNKS) g_bsum[t] = v;
    if (t == 0) g_off[N_NODES] = N_EDGES;
}

__global__ void k_chunkscan() {
    __shared__ int s[1024];
    int b = blockIdx.x, t = threadIdx.x;
    int idx = b * SCAN_CHUNK + t;
    int v = (idx < N_NODES) ? g_deg[idx] : 0;
    s[t] = v;
    __syncthreads();
    for (int d = 1; d < 1024; d <<= 1) {
        int u = (t >= d) ? s[t - d] : 0;
        __syncthreads();
        s[t] += u;
        __syncthreads();
    }
    if (idx < N_NODES) {
        int o = g_bsum[b] + s[t] - v;  // exclusive
        g_off[idx] = o;
        g_cur[idx] = o;
    }
}

__global__ void k_fill(const int* __restrict__ ei) {
    int e = blockIdx.x * blockDim.x + threadIdx.x;
    if (e >= N_EDGES) return;
    int r = ei[e];
    int c = ei[N_EDGES + e];
    int pos = atomicAdd(&g_cur[c], 1);
    g_src[pos] = r;
    g_nrm[pos] = g_dinv[r] * g_dinv[c];
}

// ---------------- h init ----------------
__global__ void k_init_h(const int* __restrict__ x,
                         const float* __restrict__ emb1,
                         const float* __restrict__ emb2) {
    int v = blockIdx.x;
    int t = threadIdx.x;
    if (t >= EMB4) return;
    int x0 = x[v * 2];
    int x1 = x[v * 2 + 1];
    float4 a = ((const float4*)(emb1 + (size_t)x0 * EMB))[t];
    float4 b = ((const float4*)(emb2 + (size_t)x1 * EMB))[t];
    float4 o;
    o.x = a.x + b.x; o.y = a.y + b.y; o.z = a.z + b.z; o.w = a.w + b.w;
    ((float4*)(g_h + (size_t)v * EMB))[t] = o;
}

// ---------------- aggregation: warp-per-node, fused BN+ReLU, bf16-split output ----------------
__global__ void k_agg(int mode) {
    int warp = (blockIdx.x * blockDim.x + threadIdx.x) >> 5;
    int lane = threadIdx.x & 31;
    if (warp >= N_NODES) return;
    bool third = (lane < EMB4 - 64);

    float4 sc0 = {1,1,1,1}, sc1 = {1,1,1,1}, sc2 = {1,1,1,1};
    float4 sh0 = {0,0,0,0}, sh1 = {0,0,0,0}, sh2 = {0,0,0,0};
    if (mode) {
        sc0 = ((const float4*)g_scale)[lane];
        sc1 = ((const float4*)g_scale)[lane + 32];
        sh0 = ((const float4*)g_shift)[lane];
        sh1 = ((const float4*)g_shift)[lane + 32];
        if (third) {
            sc2 = ((const float4*)g_scale)[lane + 64];
            sh2 = ((const float4*)g_shift)[lane + 64];
        }
    }

#define APPLY(v, sc, sh)                                           \
    if (mode) {                                                    \
        v.x = fmaxf(fmaf(v.x, sc.x, sh.x), 0.0f);                  \
        v.y = fmaxf(fmaf(v.y, sc.y, sh.y), 0.0f);                  \
        v.z = fmaxf(fmaf(v.z, sc.z, sh.z), 0.0f);                  \
        v.w = fmaxf(fmaf(v.w, sc.w, sh.w), 0.0f);                  \
    }

    float di = g_dinv[warp];
    float dsq = di * di;
    float4 acc0 = {0,0,0,0}, acc1 = {0,0,0,0}, acc2 = {0,0,0,0};
    {
        const float4* hv = (const float4*)(g_h + (size_t)warp * EMB);
        float4 t0 = hv[lane];
        float4 t1 = hv[lane + 32];
        APPLY(t0, sc0, sh0); APPLY(t1, sc1, sh1);
        acc0.x = dsq * t0.x; acc0.y = dsq * t0.y; acc0.z = dsq * t0.z; acc0.w = dsq * t0.w;
        acc1.x = dsq * t1.x; acc1.y = dsq * t1.y; acc1.z = dsq * t1.z; acc1.w = dsq * t1.w;
        if (third) {
            float4 t2 = hv[lane + 64];
            APPLY(t2, sc2, sh2);
            acc2.x = dsq * t2.x; acc2.y = dsq * t2.y; acc2.z = dsq * t2.z; acc2.w = dsq * t2.w;
        }
    }
    int e0 = g_off[warp], e1 = g_off[warp + 1];
#pragma unroll 2
    for (int e = e0; e < e1; e++) {
        int s = g_src[e];
        float w = g_nrm[e];
        const float4* hs = (const float4*)(g_h + (size_t)s * EMB);
        float4 t0 = hs[lane];
        float4 t1 = hs[lane + 32];
        APPLY(t0, sc0, sh0); APPLY(t1, sc1, sh1);
        acc0.x += w * t0.x; acc0.y += w * t0.y; acc0.z += w * t0.z; acc0.w += w * t0.w;
        acc1.x += w * t1.x; acc1.y += w * t1.y; acc1.z += w * t1.z; acc1.w += w * t1.w;
        if (third) {
            float4 t2 = hs[lane + 64];
            APPLY(t2, sc2, sh2);
            acc2.x += w * t2.x; acc2.y += w * t2.y; acc2.z += w * t2.z; acc2.w += w * t2.w;
        }
    }
#undef APPLY
    // write split (hi,lo) bf16x2 pairs: pair kp covers cols 2kp..2kp+1
    uint2* ap = g_aggP + (size_t)warp * EMBP;
    unsigned h0, l0, h1, l1;
    split_bf2(acc0.x, acc0.y, h0, l0);
    split_bf2(acc0.z, acc0.w, h1, l1);
    *(uint4*)&ap[2 * lane] = make_uint4(h0, l0, h1, l1);
    split_bf2(acc1.x, acc1.y, h0, l0);
    split_bf2(acc1.z, acc1.w, h1, l1);
    *(uint4*)&ap[64 + 2 * lane] = make_uint4(h0, l0, h1, l1);
    if (third) {
        split_bf2(acc2.x, acc2.y, h0, l0);
        split_bf2(acc2.z, acc2.w, h1, l1);
        *(uint4*)&ap[128 + 2 * lane] = make_uint4(h0, l0, h1, l1);
    }
}

// ---------------- stats ----------------
__global__ void k_zero_stats() {
    int i = threadIdx.x;
    if (i < EMB) { g_colsum[i] = 0.0f; g_colsq[i] = 0.0f; }
}

__global__ void k_finstats(const float* __restrict__ gamma,
                           const float* __restrict__ beta) {
    int c = threadIdx.x;
    if (c >= EMB) return;
    const float invN = 1.0f / (float)N_NODES;
    float mean = g_colsum[c] * invN;
    float var = g_colsq[c] * invN - mean * mean;
    float sc = gamma[c] * rsqrtf(var + BN_EPS);
    g_scale[c] = sc;
    g_shift[c] = beta[c] - mean * sc;
}

// ---- split-BF16 GEMM: A pre-split pairs from g_aggP, LDS.64 operands, zero in-loop ALU ----
#define GM 128
#define GN 64
#define GK 32
#define TKP 16       // k-pairs per tile (GK/2)
#define PP 20        // uint2 pitch per row: (m*20+kh) mod 16 = 4*r0+cc -> conflict-free
#define A_U2 (2 * GM * PP)   // 5120 uint2
#define B_U2 (2 * GN * PP)   // 2560 uint2
#define GEMM_SMEM_BYTES ((A_U2 + B_U2) * 8)  // 61440

#define MMAB(d, A0, A1, A2, A3, B0, B1)                                        \
    asm volatile(                                                              \
        "mma.sync.aligned.m16n8k16.row.col.f32.bf16.bf16.f32 "                 \
        "{%0,%1,%2,%3}, {%4,%5,%6,%7}, {%8,%9}, {%0,%1,%2,%3};\n"              \
        : "+f"(d[0]), "+f"(d[1]), "+f"(d[2]), "+f"(d[3])                       \
        : "r"(A0), "r"(A1), "r"(A2), "r"(A3), "r"(B0), "r"(B1))

__global__ __launch_bounds__(256, 2)
void k_gemm_bf16(const float* __restrict__ W, const float* __restrict__ bias) {
    extern __shared__ __align__(16) uint2 smp[];
    uint2* AsP = smp;            // [2][GM][PP]  (m, kp) -> (hi, lo)
    uint2* BsP = smp + A_U2;     // [2][GN][PP]  (n, kp) -> (hi, lo)

    float* C = g_h;

    int tid = threadIdx.x;
    int warp = tid >> 5, lane = tid & 31;
    int r0 = lane >> 2, cc = lane & 3;
    int mBase = blockIdx.y * GM;
    int nBase = blockIdx.x * GN;
    int warpM = (warp & 3) * 32;
    int warpN = (warp >> 2) * 32;

    float acc[2][4][4];
#pragma unroll
    for (int mi = 0; mi < 2; mi++)
#pragma unroll
        for (int ni = 0; ni < 4; ni++)
#pragma unroll
            for (int i = 0; i < 4; i++) acc[mi][ni][i] = 0.0f;

    // A copy map: row = tid>>1, 8 pairs starting at (tid&1)*8, as 4 uint4
    int aRow = tid >> 1;
    int aKpb = (tid & 1) * 8;
    // B fill map: n = tid&63, 4 pairs starting at (tid>>6)*4
    int bN = tid & 63;
    int bKpb = (tid >> 6) * 4;
    const int NKT = 10;  // 10 * 16 pairs = 160 >= 150

    uint4 pa[4];
    float pb0[4], pb1[4];

#define LOAD_TILE(kt)                                                          \
    {                                                                          \
        int grow = mBase + aRow;                                               \
        bool rok = grow < N_NODES;                                             \
        _Pragma("unroll")                                                      \
        for (int i = 0; i < 4; i++) {                                          \
            int kpg = (kt) * TKP + aKpb + i * 2;                               \
            if (rok && kpg < EMBP)                                             \
                pa[i] = *(const uint4*)&g_aggP[(size_t)grow * EMBP + kpg];     \
            else                                                               \
                pa[i] = make_uint4(0, 0, 0, 0);                                \
        }                                                                      \
        int gn = nBase + bN;                                                   \
        _Pragma("unroll")                                                      \
        for (int j = 0; j < 4; j++) {                                          \
            int gk = (kt) * GK + 2 * (bKpb + j);                               \
            pb0[j] = (gk < EMB && gn < EMB) ? W[(size_t)gk * EMB + gn] : 0.0f; \
            pb1[j] = (gk + 1 < EMB && gn < EMB) ? W[(size_t)(gk + 1) * EMB + gn] : 0.0f; \
        }                                                                      \
    }

#define STORE_TILE(buf)                                                        \
    {                                                                          \
        int ab = (buf) * (GM * PP) + aRow * PP + aKpb;                         \
        _Pragma("unroll")                                                      \
        for (int i = 0; i < 4; i++)                                            \
            *(uint4*)&AsP[ab + i * 2] = pa[i];                                 \
        int bb = (buf) * (GN * PP) + bN * PP + bKpb;                           \
        _Pragma("unroll")                                                      \
        for (int j = 0; j < 4; j++) {                                          \
            unsigned h, l;                                                     \
            split_bf2(pb0[j], pb1[j], h, l);                                   \
            BsP[bb + j] = make_uint2(h, l);                                    \
        }                                                                      \
    }

    LOAD_TILE(0);
    STORE_TILE(0);
    __syncthreads();

    for (int kt = 0; kt < NKT; kt++) {
        int buf = kt & 1;
        if (kt + 1 < NKT) LOAD_TILE(kt + 1);
        int aub = buf * (GM * PP);
        int bub = buf * (GN * PP);
#pragma unroll
        for (int ks = 0; ks < 2; ks++) {
            int kh = ks * 8 + cc;
            unsigned ah[2][4], al[2][4], bh[4][2], bl[4][2];
#pragma unroll
            for (int mi = 0; mi < 2; mi++) {
                int mr = warpM + mi * 16 + r0;
                uint2 u0 = AsP[aub + mr * PP + kh];
                uint2 u1 = AsP[aub + (mr + 8) * PP + kh];
                uint2 u2 = AsP[aub + mr * PP + kh + 4];
                uint2 u3 = AsP[aub + (mr + 8) * PP + kh + 4];
                ah[mi][0] = u0.x; al[mi][0] = u0.y;
                ah[mi][1] = u1.x; al[mi][1] = u1.y;
                ah[mi][2] = u2.x; al[mi][2] = u2.y;
                ah[mi][3] = u3.x; al[mi][3] = u3.y;
            }
#pragma unroll
            for (int ni = 0; ni < 4; ni++) {
                int nc = warpN + ni * 8 + r0;
                uint2 v0 = BsP[bub + nc * PP + kh];
                uint2 v1 = BsP[bub + nc * PP + kh + 4];
                bh[ni][0] = v0.x; bl[ni][0] = v0.y;
                bh[ni][1] = v1.x; bl[ni][1] = v1.y;
            }
#pragma unroll
            for (int mi = 0; mi < 2; mi++)
#pragma unroll
                for (int ni = 0; ni < 4; ni++) {
                    // small terms first, hi*hi last
                    MMAB(acc[mi][ni], al[mi][0], al[mi][1], al[mi][2], al[mi][3],
                         bh[ni][0], bh[ni][1]);
                    MMAB(acc[mi][ni], ah[mi][0], ah[mi][1], ah[mi][2], ah[mi][3],
                         bl[ni][0], bl[ni][1]);
                    MMAB(acc[mi][ni], ah[mi][0], ah[mi][1], ah[mi][2], ah[mi][3],
                         bh[ni][0], bh[ni][1]);
                }
        }
        if (kt + 1 < NKT) STORE_TILE(1 - buf);
        __syncthreads();
    }

    // epilogue: bias, store, column stats (shfl-reduced before global atomics)
#pragma unroll
    for (int ni = 0; ni < 4; ni++) {
        int gcol = nBase + warpN + ni * 8 + 2 * cc;
        bool cok = gcol < EMB;  // gcol even, EMB even -> gcol+1 valid too
        float b0 = cok ? bias[gcol] : 0.0f;
        float b1 = cok ? bias[gcol + 1] : 0.0f;
        float s0 = 0.0f, s1 = 0.0f, q0 = 0.0f, q1 = 0.0f;
#pragma unroll
        for (int mi = 0; mi < 2; mi++) {
            int grow0 = mBase + warpM + mi * 16 + r0;
            int grow1 = grow0 + 8;
            float v00 = acc[mi][ni][0] + b0;
            float v01 = acc[mi][ni][1] + b1;
            float v10 = acc[mi][ni][2] + b0;
            float v11 = acc[mi][ni][3] + b1;
            if (cok && grow0 < N_NODES) {
                *(float2*)(C + (size_t)grow0 * EMB + gcol) = make_float2(v00, v01);
                s0 += v00; s1 += v01; q0 += v00 * v00; q1 += v01 * v01;
            }
            if (cok && grow1 < N_NODES) {
                *(float2*)(C + (size_t)grow1 * EMB + gcol) = make_float2(v10, v11);
                s0 += v10; s1 += v11; q0 += v10 * v10; q1 += v11 * v11;
            }
        }
#pragma unroll
        for (int d = 4; d < 32; d <<= 1) {
            s0 += __shfl_xor_sync(0xffffffffu, s0, d);
            s1 += __shfl_xor_sync(0xffffffffu, s1, d);
            q0 += __shfl_xor_sync(0xffffffffu, q0, d);
            q1 += __shfl_xor_sync(0xffffffffu, q1, d);
        }
        if (r0 == 0 && cok) {
            atomicAdd(&g_colsum[gcol], s0);
            atomicAdd(&g_colsum[gcol + 1], s1);
            atomicAdd(&g_colsq[gcol], q0);
            atomicAdd(&g_colsq[gcol + 1], q1);
        }
    }
#undef LOAD_TILE
#undef STORE_TILE
}

// ---------------- pooling (fused final BN, no relu) ----------------
__global__ void k_zero_pool() {
    int i = blockIdx.x * blockDim.x + threadIdx.x;
    if (i < N_GRAPHS * EMB) g_pool[i] = 0.0f;
    if (i < N_GRAPHS) g_cnt[i] = 0.0f;
}

__global__ void k_count(const int* __restrict__ batch) {
    int i = blockIdx.x * blockDim.x + threadIdx.x;
    if (i < N_NODES) atomicAdd(&g_cnt[batch[i]], 1.0f);
}

#define PCHUNK 256
__global__ void k_poolsum(const int* __restrict__ batch) {
    __shared__ int sb[PCHUNK];
    int t = threadIdx.x;
    int base = blockIdx.x * PCHUNK;
    int end = base + PCHUNK;
    if (end > N_NODES) end = N_NODES;
    int len = end - base;
    for (int i = t; i < len; i += blockDim.x) sb[i] = batch[base + i];
    __syncthreads();
    if (t >= EMB) return;
    float sc = g_scale[t], sh = g_shift[t];
    float acc = 0.0f;
    int cur = sb[0];
    for (int n = 0; n < len; n++) {
        int gph = sb[n];
        if (gph != cur) {
            atomicAdd(&g_pool[(size_t)cur * EMB + t], acc);
            acc = 0.0f;
            cur = gph;
        }
        acc += fmaf(g_h[(size_t)(base + n) * EMB + t], sc, sh);
    }
    atomicAdd(&g_pool[(size_t)cur * EMB + t], acc);
}

// ---------------- final projection ----------------
__global__ void k_final(const float* __restrict__ Wf,
                        const float* __restrict__ bf,
                        float* __restrict__ out) {
    __shared__ float p[EMB];
    int gph = blockIdx.x;
    int f = threadIdx.x;
    float inv = 1.0f / fmaxf(g_cnt[gph], 1.0f);
    for (int j = f; j < EMB; j += FEAT) p[j] = g_pool[(size_t)gph * EMB + j] * inv;
    __syncthreads();
    float acc = bf[f];
#pragma unroll 4
    for (int j = 0; j < EMB; j++) acc += p[j] * Wf[(size_t)j * FEAT + f];
    out[(size_t)gph * FEAT + f] = acc;
}

// ---------------- launcher ----------------
extern "C" void kernel_launch(void* const* d_in, const int* in_sizes, int n_in,
                              void* d_out, int out_size) {
    const int*   x      = (const int*)d_in[0];
    const int*   ei     = (const int*)d_in[1];
    const int*   batch  = (const int*)d_in[2];
    const float* emb1   = (const float*)d_in[3];
    const float* emb2   = (const float*)d_in[4];
    const float* Ws     = (const float*)d_in[5];
    const float* bs     = (const float*)d_in[6];
    const float* gammas = (const float*)d_in[7];
    const float* betas  = (const float*)d_in[8];
    const float* Wf     = (const float*)d_in[9];
    const float* bf     = (const float*)d_in[10];
    float* out = (float*)d_out;

    cudaFuncSetAttribute(k_gemm_bf16,
                         cudaFuncAttributeMaxDynamicSharedMemorySize,
                         GEMM_SMEM_BYTES);

    // graph preprocessing (CSR by destination)
    k_zero_deg<<<(N_NODES + 255) / 256, 256>>>();
    k_hist<<<(N_EDGES + 255) / 256, 256>>>(ei);
    k_dinv<<<(N_NODES + 255) / 256, 256>>>();
    k_chunksum<<<N_CHUNKS, 1024>>>();
    k_scanb<<<1, 128>>>();
    k_chunkscan<<<N_CHUNKS, 1024>>>();
    k_fill<<<(N_EDGES + 255) / 256, 256>>>(ei);

    // h init
    k_init_h<<<N_NODES, 96>>>(x, emb1, emb2);

    dim3 gemmGrid((EMB + GN - 1) / GN, (N_NODES + GM - 1) / GM);  // n fastest: A tile L2-reuse
    for (int l = 0; l < N_LAYERS; l++) {
        const float* W = Ws + (size_t)l * EMB * EMB;
        const float* b = bs + (size_t)l * EMB;
        const float* gamma = gammas + (size_t)l * EMB;
        const float* beta = betas + (size_t)l * EMB;
        k_agg<<<(N_NODES * 32 + 255) / 256, 256>>>(l == 0 ? 0 : 1);
        k_zero_stats<<<1, 320>>>();
        k_gemm_bf16<<<gemmGrid, 256, GEMM_SMEM_BYTES>>>(W, b);
        k_finstats<<<1, 320>>>(gamma, beta);
    }

    // pooling (applies final BN) + projection
    k_zero_pool<<<(N_GRAPHS * EMB + 255) / 256, 256>>>();
    k_count<<<(N_NODES + 255) / 256, 256>>>(batch);
    k_poolsum<<<(N_NODES + PCHUNK - 1) / PCHUNK, 320>>>(batch);
    k_final<<<N_GRAPHS, FEAT>>>(Wf, bf, out);
}